// round 17
// baseline (speedup 1.0000x reference)
#include <cuda_runtime.h>
#include <cuda_bf16.h>
#include <cstdint>
#include <math.h>

constexpr int B_  = 4;
constexpr int C_  = 256;
constexpr int C8_ = 32;
constexpr int N_  = 4096;
constexpr int K_  = 3;

constexpr int TI = 64;    // queries per CTA
constexpr int TJ = 64;    // keys per j-step
constexpr int NSTEP = N_ / TJ;

// ---- scratch (device globals; no allocation allowed) ----------------------
__device__ __nv_bfloat16 g_q[(size_t)K_ * B_ * N_ * C8_];    // [zb][n][o]
__device__ __nv_bfloat16 g_k[(size_t)B_ * N_ * C8_];         // [b][n][o]
__device__ __nv_bfloat16 g_v[(size_t)K_ * B_ * C_ * N_];     // [zb][c][n]
__device__ __nv_bfloat16 g_accs[(size_t)K_ * B_ * N_ * C_];  // [zb][n][c] bf16 slabs
__device__ __nv_bfloat16 g_accsum[(size_t)B_ * N_ * C_];     // [b][n][c] bf16 sum
// precomputed bf16 weights
__device__ __nv_bfloat16 g_wvb[256 * 256];                   // Wv bf16 [c][k]
__device__ __nv_bfloat16 g_wqb[32 * 256];                    // Wq bf16 [o][k]
__device__ __nv_bfloat16 g_wkb[32 * 256];                    // Wk bf16 [o][k]
__device__ __nv_bfloat16 g_wfa[256 * 256];                   // gamma * Wf[:, :256]
__device__ __nv_bfloat16 g_wfx_hi[256 * 256];                // hi(Wf[:, 256:])
__device__ __nv_bfloat16 g_wfx_lo[256 * 256];                // lo(Wf[:, 256:])
__device__ __nv_bfloat16 g_xhi [(size_t)B_ * N_ * C_];       // [b][n][c]
__device__ __nv_bfloat16 g_xlo [(size_t)B_ * N_ * C_];       // [b][n][c]

// ---- helpers --------------------------------------------------------------
__device__ __forceinline__ uint32_t smem_u32(const void* p) {
    uint32_t a;
    asm("{ .reg .u64 t; cvta.to.shared.u64 t, %1; cvt.u32.u64 %0, t; }" : "=r"(a) : "l"(p));
    return a;
}
__device__ __forceinline__ void ldsm4(uint32_t* r, uint32_t addr) {
    asm volatile("ldmatrix.sync.aligned.m8n8.x4.shared.b16 {%0,%1,%2,%3}, [%4];"
                 : "=r"(r[0]), "=r"(r[1]), "=r"(r[2]), "=r"(r[3]) : "r"(addr));
}
__device__ __forceinline__ void mma16816(float* d, const uint32_t* a, uint32_t b0, uint32_t b1) {
    asm volatile("mma.sync.aligned.m16n8k16.row.col.f32.bf16.bf16.f32 "
                 "{%0,%1,%2,%3}, {%4,%5,%6,%7}, {%8,%9}, {%0,%1,%2,%3};"
                 : "+f"(d[0]), "+f"(d[1]), "+f"(d[2]), "+f"(d[3])
                 : "r"(a[0]), "r"(a[1]), "r"(a[2]), "r"(a[3]), "r"(b0), "r"(b1));
}
__device__ __forceinline__ uint32_t packbf2(float x, float y) {
    __nv_bfloat162 h = __float22bfloat162_rn(make_float2(x, y));
    return *(uint32_t*)&h;
}
__device__ __forceinline__ void cp16(uint32_t dst, const void* src) {
    asm volatile("cp.async.cg.shared.global [%0], [%1], 16;" :: "r"(dst), "l"(src));
}
#define CP_COMMIT() asm volatile("cp.async.commit_group;" ::: "memory")
#define CP_WAIT1()  asm volatile("cp.async.wait_group 1;" ::: "memory")

// ---- attn smem layout -----------------------------------------------------
constexpr int QROW = 80;
constexpr int KROW = 80;
constexpr int VROW = 144;
constexpr int SM_Q  = 0;
constexpr int SM_K0 = 5120;
constexpr int VOFF  = 64 * KROW;
constexpr int BUFD  = VOFF + C_ * VROW;        // 41984
constexpr int SM_TOTAL = SM_K0 + 2 * BUFD;     // 89088

// ---------------------------------------------------------------------------
// attention: grid (N/64, K*B); epilogue writes bf16 transposed slab directly.
__global__ void __launch_bounds__(128, 2) attn_kernel() {
    extern __shared__ char smem[];
    uint32_t sb = smem_u32(smem);
    int tid = threadIdx.x, wid = tid >> 5, lane = tid & 31;
    int g = lane >> 2, m = lane & 3;
    int zb = blockIdx.y;
    int b = zb & 3;
    int itile = blockIdx.x * TI;
    int wrow = wid * 16;

    uint32_t qaddr = sb + SM_Q + (wrow + (lane & 15)) * QROW + ((lane >> 4) & 1) * 16;
    uint32_t koff = ((lane >> 4) * 8 + (lane & 7)) * KROW + ((lane >> 3) & 1) * 16;
    uint32_t voff = VOFF + ((lane >> 4) * 8 + (lane & 7)) * VROW + ((lane >> 3) & 1) * 16;

    const __nv_bfloat16* kbase = g_k + (size_t)b * N_ * C8_;
    const __nv_bfloat16* vbase = g_v + (size_t)zb * C_ * N_;

    const __nv_bfloat16* qp = g_q + ((size_t)zb * N_ + itile) * C8_;
    for (int t = tid; t < 256; t += 128) {
        int r = t >> 2, ch = t & 3;
        *(uint4*)(smem + SM_Q + r * QROW + ch * 16) = *(const uint4*)(qp + r * C8_ + ch * 8);
    }

    {
        uint32_t bufb = sb + SM_K0;
#pragma unroll
        for (int i = 0; i < 2; i++) {
            int t = tid + 128 * i;
            int r = t >> 2, ch = t & 3;
            cp16(bufb + r * KROW + ch * 16, kbase + (size_t)r * C8_ + ch * 8);
        }
#pragma unroll
        for (int i = 0; i < 16; i++) {
            int t = tid + 128 * i;
            int c = t >> 3, ch = t & 7;
            cp16(bufb + VOFF + c * VROW + ch * 16, vbase + (size_t)c * N_ + ch * 8);
        }
        CP_COMMIT();
    }

    __syncthreads();
    uint32_t qa[2][4];
    ldsm4(qa[0], qaddr);
    ldsm4(qa[1], qaddr + 32);

    float Dn[32][4];
#pragma unroll
    for (int c = 0; c < 32; c++)
#pragma unroll
        for (int p = 0; p < 4; p++) Dn[c][p] = 0.f;
    float den0 = 0.f, den1 = 0.f;

    for (int js = 0; js < NSTEP; js++) {
        uint32_t bufb = sb + SM_K0 + (js & 1) * BUFD;
        if (js + 1 < NSTEP) {
            int jt2 = (js + 1) * TJ;
            uint32_t nb = sb + SM_K0 + ((js + 1) & 1) * BUFD;
#pragma unroll
            for (int i = 0; i < 2; i++) {
                int t = tid + 128 * i;
                int r = t >> 2, ch = t & 3;
                cp16(nb + r * KROW + ch * 16, kbase + (size_t)(jt2 + r) * C8_ + ch * 8);
            }
#pragma unroll
            for (int i = 0; i < 16; i++) {
                int t = tid + 128 * i;
                int c = t >> 3, ch = t & 7;
                cp16(nb + VOFF + c * VROW + ch * 16, vbase + (size_t)c * N_ + jt2 + ch * 8);
            }
        }
        CP_COMMIT();
        CP_WAIT1();
        __syncthreads();

        float s[8][4];
#pragma unroll
        for (int j = 0; j < 8; j++)
#pragma unroll
            for (int p = 0; p < 4; p++) s[j][p] = 0.f;
#pragma unroll
        for (int kc = 0; kc < 2; kc++) {
#pragma unroll
            for (int jp = 0; jp < 4; jp++) {
                uint32_t kb[4];
                ldsm4(kb, bufb + koff + jp * 16 * KROW + kc * 32);
                mma16816(s[2 * jp],     qa[kc], kb[0], kb[1]);
                mma16816(s[2 * jp + 1], qa[kc], kb[2], kb[3]);
            }
        }
        uint32_t pa[8], pb[8];
#pragma unroll
        for (int j = 0; j < 8; j++) {
            float e0 = __expf(s[j][0]), e1 = __expf(s[j][1]);
            float e2 = __expf(s[j][2]), e3 = __expf(s[j][3]);
            den0 += e0 + e1;
            den1 += e2 + e3;
            pa[j] = packbf2(e0, e1);
            pb[j] = packbf2(e2, e3);
        }
#pragma unroll
        for (int tp = 0; tp < 4; tp++) {
            uint32_t af[4] = {pa[2 * tp], pb[2 * tp], pa[2 * tp + 1], pb[2 * tp + 1]};
#pragma unroll
            for (int vp = 0; vp < 16; vp++) {
                uint32_t vb[4];
                ldsm4(vb, bufb + voff + vp * 16 * VROW + tp * 32);
                mma16816(Dn[2 * vp],     af, vb[0], vb[1]);
                mma16816(Dn[2 * vp + 1], af, vb[2], vb[3]);
            }
        }
        __syncthreads();
    }

    den0 += __shfl_xor_sync(0xffffffffu, den0, 1);
    den0 += __shfl_xor_sync(0xffffffffu, den0, 2);
    den1 += __shfl_xor_sync(0xffffffffu, den1, 1);
    den1 += __shfl_xor_sync(0xffffffffu, den1, 2);
    float inv0 = 1.f / den0, inv1 = 1.f / den1;

    // normalize + bf16 transposed store into g_accs[zb][n][c]
    int n0 = itile + wrow + g;
    uint32_t* r0 = (uint32_t*)(g_accs + ((size_t)zb * N_ + n0) * C_);
    uint32_t* r1 = (uint32_t*)(g_accs + ((size_t)zb * N_ + n0 + 8) * C_);
#pragma unroll
    for (int ct = 0; ct < 32; ct++) {
        int c = 8 * ct + 2 * m;
        r0[c >> 1] = packbf2(Dn[ct][0] * inv0, Dn[ct][1] * inv0);
        r1[c >> 1] = packbf2(Dn[ct][2] * inv1, Dn[ct][3] * inv1);
    }
}

// ---------------------------------------------------------------------------
// prep_w: all weight conversions, once. grid 256, 128 threads.
__global__ void __launch_bounds__(128) prep_w(const float* __restrict__ Wf,
                                              const float* __restrict__ gptr,
                                              const float* __restrict__ Wq,
                                              const float* __restrict__ Wk,
                                              const float* __restrict__ Wv) {
    int o = blockIdx.x;
    int tid = threadIdx.x;
    float gamma = gptr[0];
    {
        int c4 = tid * 4;
        float4 w = *(const float4*)(Wf + (size_t)o * 512 + c4);
        if (c4 < 256) {
            *(uint32_t*)(g_wfa + (size_t)o * 256 + c4)     = packbf2(gamma * w.x, gamma * w.y);
            *(uint32_t*)(g_wfa + (size_t)o * 256 + c4 + 2) = packbf2(gamma * w.z, gamma * w.w);
        } else {
            int c = c4 - 256;
            float h0 = __bfloat162float(__float2bfloat16(w.x));
            float h1 = __bfloat162float(__float2bfloat16(w.y));
            float h2 = __bfloat162float(__float2bfloat16(w.z));
            float h3 = __bfloat162float(__float2bfloat16(w.w));
            *(uint32_t*)(g_wfx_hi + (size_t)o * 256 + c)     = packbf2(w.x, w.y);
            *(uint32_t*)(g_wfx_hi + (size_t)o * 256 + c + 2) = packbf2(w.z, w.w);
            *(uint32_t*)(g_wfx_lo + (size_t)o * 256 + c)     = packbf2(w.x - h0, w.y - h1);
            *(uint32_t*)(g_wfx_lo + (size_t)o * 256 + c + 2) = packbf2(w.z - h2, w.w - h3);
        }
    }
    {
        int c = tid * 2;
        float2 w = *(const float2*)(Wv + (size_t)o * 256 + c);
        *(uint32_t*)(g_wvb + (size_t)o * 256 + c) = packbf2(w.x, w.y);
    }
    if (o < 32) {
        int c = tid * 2;
        float2 wq = *(const float2*)(Wq + (size_t)o * 256 + c);
        float2 wk = *(const float2*)(Wk + (size_t)o * 256 + c);
        *(uint32_t*)(g_wqb + (size_t)o * 256 + c) = packbf2(wq.x, wq.y);
        *(uint32_t*)(g_wkb + (size_t)o * 256 + c) = packbf2(wk.x, wk.y);
    }
}

// ---------------------------------------------------------------------------
// prep_sum: g_accsum = bf16(sum of 3 slabs), fp32 adds. 8 bf16 per thread.
__global__ void __launch_bounds__(256) prep_sum() {
    constexpr size_t SL = (size_t)B_ * N_ * C_;
    size_t off = ((size_t)blockIdx.x * 256 + threadIdx.x) * 8;
    uint4 u0 = *(const uint4*)(g_accs + off);
    uint4 u1 = *(const uint4*)(g_accs + SL + off);
    uint4 u2 = *(const uint4*)(g_accs + 2 * SL + off);
    uint4 r;
    const uint32_t* a0 = (const uint32_t*)&u0;
    const uint32_t* a1 = (const uint32_t*)&u1;
    const uint32_t* a2 = (const uint32_t*)&u2;
    uint32_t* rp = (uint32_t*)&r;
#pragma unroll
    for (int i = 0; i < 4; i++) {
        __nv_bfloat162 h0 = *(__nv_bfloat162*)&a0[i];
        __nv_bfloat162 h1 = *(__nv_bfloat162*)&a1[i];
        __nv_bfloat162 h2 = *(__nv_bfloat162*)&a2[i];
        float lo = __bfloat162float(h0.x) + __bfloat162float(h1.x) + __bfloat162float(h2.x);
        float hi = __bfloat162float(h0.y) + __bfloat162float(h1.y) + __bfloat162float(h2.y);
        rp[i] = packbf2(lo, hi);
    }
    *(uint4*)(g_accsum + off) = r;
}

// ---------------------------------------------------------------------------
// proj_all: cp.async double-buffered; isK CTAs also emit g_xhi/g_xlo tiles.
constexpr int PROW2 = 144;
constexpr int XSROW = 528;                       // 128 floats + 16B pad
constexpr int OFF_WV = 0;                        // 256 * 144 = 36864
constexpr int OFF_WQ = 36864;                    // 32 * 144  = 4608
constexpr int OFF_XS = 41472;                    // 64 * 528  = 33792
constexpr int PBUF   = 75264;
constexpr int OFF_XT = 2 * PBUF;                 // 150528; 128*144 = 18432
constexpr int SMP_TOTAL = OFF_XT + 128 * PROW2;  // 168960

__global__ void __launch_bounds__(256, 1) proj_all(const float* __restrict__ xball,
                                                   const float* __restrict__ xf,
                                                   const float* __restrict__ bq,
                                                   const float* __restrict__ bk,
                                                   const float* __restrict__ bv) {
    extern __shared__ char psm[];
    uint32_t sb = smem_u32(psm);
    uint32_t xt_b = sb + OFF_XT;
    int tid = threadIdx.x, wid = tid >> 5, lane = tid & 31;
    int g = lane >> 2, m = lane & 3;
    int z = blockIdx.z;
    int n0 = blockIdx.x * 128;
    bool isK = (z >= K_ * B_);
    int bloc = z - K_ * B_;
    const float* xb = isK ? (xf + (size_t)bloc * C_ * N_)
                          : (xball + (size_t)z * C_ * N_);
    const __nv_bfloat16* Wqkb = isK ? g_wkb : g_wqb;
    const float* bqk = isK ? bk : bq;

    int wrowv = wid * 32;
    uint32_t woff = OFF_WV + (wrowv + (lane & 15)) * PROW2 + ((lane >> 4) & 1) * 16;
    uint32_t xoffB = ((lane >> 4) * 8 + (lane & 7)) * PROW2 + ((lane >> 3) & 1) * 16;
    uint32_t xoffA = (wid * 16 + (lane & 15)) * PROW2 + ((lane >> 4) & 1) * 16;
    uint32_t qwoff = OFF_WQ + ((lane >> 4) * 8 + (lane & 7)) * PROW2 + ((lane >> 3) & 1) * 16;

    float accv[2][16][4];
    if (!isK) {
#pragma unroll
        for (int t = 0; t < 2; t++) {
            float b0 = bv[wrowv + t * 16 + g];
            float b1 = bv[wrowv + t * 16 + g + 8];
#pragma unroll
            for (int nt = 0; nt < 16; nt++) {
                accv[t][nt][0] = b0; accv[t][nt][1] = b0;
                accv[t][nt][2] = b1; accv[t][nt][3] = b1;
            }
        }
    }
    float accq[4][4];
#pragma unroll
    for (int j = 0; j < 4; j++) {
        int o = j * 8 + 2 * m;
        float b0 = bqk[o], b1 = bqk[o + 1];
        accq[j][0] = b0; accq[j][1] = b1;
        accq[j][2] = b0; accq[j][3] = b1;
    }

    auto load_step = [&](int ks, uint32_t bufb) {
        int k0 = ks * 64;
        if (!isK) {
#pragma unroll
            for (int i = 0; i < 8; i++) {
                int idx = tid + 256 * i;
                int r = idx >> 3, ch = idx & 7;
                cp16(bufb + OFF_WV + r * PROW2 + ch * 16,
                     g_wvb + (size_t)r * 256 + k0 + ch * 8);
            }
        }
        {
            int r = tid >> 3, ch = tid & 7;
            if (r < 32)
                cp16(bufb + OFF_WQ + r * PROW2 + ch * 16,
                     Wqkb + (size_t)r * 256 + k0 + ch * 8);
        }
#pragma unroll
        for (int i = 0; i < 8; i++) {
            int idx = tid + 256 * i;
            int r = idx >> 5, ch = idx & 31;
            cp16(bufb + OFF_XS + r * XSROW + ch * 16,
                 xb + (size_t)(k0 + r) * N_ + n0 + ch * 4);
        }
    };

    load_step(0, sb);
    CP_COMMIT();

    for (int ks = 0; ks < 4; ks++) {
        int k0 = ks * 64;
        uint32_t bufb = sb + (ks & 1) * PBUF;
        if (ks + 1 < 4) load_step(ks + 1, sb + ((ks + 1) & 1) * PBUF);
        CP_COMMIT();
        CP_WAIT1();
        __syncthreads();

        // convert staging fp32 [k][n] -> xt bf16 [n][k]; isK also emits hi/lo
        {
            int n = tid & 127;
            int kgbase = (tid >> 7) * 8;
            const float* xs = (const float*)(psm + (ks & 1) * PBUF + OFF_XS);
            __nv_bfloat16* hib = g_xhi + ((size_t)bloc * N_ + n0 + n) * C_ + k0;
            __nv_bfloat16* lob = g_xlo + ((size_t)bloc * N_ + n0 + n) * C_ + k0;
#pragma unroll
            for (int kg2 = 0; kg2 < 8; kg2++) {
                int kg = kgbase + kg2;
                int k4 = kg * 4;
                float a0 = xs[(k4 + 0) * 132 + n];
                float a1 = xs[(k4 + 1) * 132 + n];
                float a2 = xs[(k4 + 2) * 132 + n];
                float a3 = xs[(k4 + 3) * 132 + n];
                uint32_t lo = packbf2(a0, a1), hi = packbf2(a2, a3);
                uint32_t d = xt_b + n * PROW2 + kg * 8;
                asm volatile("st.shared.v2.b32 [%0], {%1, %2};" :: "r"(d), "r"(lo), "r"(hi));
                if (isK) {
                    *(uint32_t*)(hib + k4)     = lo;
                    *(uint32_t*)(hib + k4 + 2) = hi;
                    float h0 = __bfloat162float(__float2bfloat16(a0));
                    float h1 = __bfloat162float(__float2bfloat16(a1));
                    float h2 = __bfloat162float(__float2bfloat16(a2));
                    float h3 = __bfloat162float(__float2bfloat16(a3));
                    *(uint32_t*)(lob + k4)     = packbf2(a0 - h0, a1 - h1);
                    *(uint32_t*)(lob + k4 + 2) = packbf2(a2 - h2, a3 - h3);
                }
            }
        }
        __syncthreads();

#pragma unroll
        for (int kc = 0; kc < 4; kc++) {
            {
                uint32_t xa[4];
                ldsm4(xa, xt_b + xoffA + kc * 32);
                uint32_t wb0[4], wb1[4];
                ldsm4(wb0, bufb + qwoff + kc * 32);
                ldsm4(wb1, bufb + qwoff + 16 * PROW2 + kc * 32);
                mma16816(accq[0], xa, wb0[0], wb0[1]);
                mma16816(accq[1], xa, wb0[2], wb0[3]);
                mma16816(accq[2], xa, wb1[0], wb1[1]);
                mma16816(accq[3], xa, wb1[2], wb1[3]);
            }
            if (!isK) {
                uint32_t af[2][4];
#pragma unroll
                for (int t = 0; t < 2; t++)
                    ldsm4(af[t], bufb + woff + t * 16 * PROW2 + kc * 32);
#pragma unroll
                for (int np = 0; np < 8; np++) {
                    uint32_t xb4[4];
                    ldsm4(xb4, xt_b + xoffB + np * 16 * PROW2 + kc * 32);
#pragma unroll
                    for (int t = 0; t < 2; t++) {
                        mma16816(accv[t][2 * np],     af[t], xb4[0], xb4[1]);
                        mma16816(accv[t][2 * np + 1], af[t], xb4[2], xb4[3]);
                    }
                }
            }
        }
    }

    {
        __nv_bfloat16* dst = (isK ? g_k + (size_t)bloc * N_ * C8_
                                  : g_q + (size_t)z * N_ * C8_) + (size_t)n0 * C8_;
        int n = wid * 16 + g;
#pragma unroll
        for (int j = 0; j < 4; j++) {
            int o = j * 8 + 2 * m;
            *(uint32_t*)(dst + (size_t)n * C8_ + o)       = packbf2(accq[j][0], accq[j][1]);
            *(uint32_t*)(dst + (size_t)(n + 8) * C8_ + o) = packbf2(accq[j][2], accq[j][3]);
        }
    }
    if (!isK) {
        __nv_bfloat16* outb = g_v + (size_t)z * C_ * N_;
#pragma unroll
        for (int t = 0; t < 2; t++) {
            int c0 = wrowv + t * 16 + g;
#pragma unroll
            for (int nt = 0; nt < 16; nt++) {
                int n = n0 + nt * 8 + 2 * m;
                *(uint32_t*)(outb + (size_t)c0 * N_ + n)       = packbf2(accv[t][nt][0], accv[t][nt][1]);
                *(uint32_t*)(outb + (size_t)(c0 + 8) * N_ + n) = packbf2(accv[t][nt][2], accv[t][nt][3]);
            }
        }
    }
}

// ---------------------------------------------------------------------------
// final_gemm: pure bf16 cp.async double-buffered GEMM over virtual k=1024.
constexpr int FROW = 144;
constexpr int FX   = 128 * FROW;
constexpr int FBUF = 2 * 128 * FROW;
constexpr int SMF_TOTAL = 2 * FBUF;

__global__ void __launch_bounds__(128, 2) final_gemm(const float* __restrict__ bfv,
                                                     float* __restrict__ out) {
    extern __shared__ char fsm[];
    uint32_t sb = smem_u32(fsm);
    int tid = threadIdx.x, wid = tid >> 5, lane = tid & 31;
    int g = lane >> 2, m = lane & 3;
    int b = blockIdx.z;
    int obase = blockIdx.y * 128;
    int n0 = blockIdx.x * 128;
    int wrow = wid * 32;

    uint32_t woff = (wrow + (lane & 15)) * FROW + ((lane >> 4) & 1) * 16;
    uint32_t xoff = FX + ((lane >> 4) * 8 + (lane & 7)) * FROW + ((lane >> 3) & 1) * 16;

    float acc[2][16][4];
#pragma unroll
    for (int t = 0; t < 2; t++) {
        float b0 = bfv[obase + wrow + t * 16 + g];
        float b1 = bfv[obase + wrow + t * 16 + g + 8];
#pragma unroll
        for (int nt = 0; nt < 16; nt++) {
            acc[t][nt][0] = b0; acc[t][nt][1] = b0;
            acc[t][nt][2] = b1; acc[t][nt][3] = b1;
        }
    }

    auto load_step = [&](int ks, uint32_t bufb) {
        int bs = ks >> 2, c64 = (ks & 3) * 64;
        const __nv_bfloat16* wp = (bs == 0) ? g_wfa : (bs == 3) ? g_wfx_lo : g_wfx_hi;
        const __nv_bfloat16* xp = ((bs == 0) ? g_accsum : (bs == 2) ? g_xlo : g_xhi)
                                  + (size_t)b * N_ * 256;
#pragma unroll
        for (int i = 0; i < 8; i++) {
            int idx = tid + 128 * i;
            int r = idx >> 3, ch = idx & 7;
            cp16(bufb + r * FROW + ch * 16,
                 wp + (size_t)(obase + r) * 256 + c64 + ch * 8);
            cp16(bufb + FX + r * FROW + ch * 16,
                 xp + (size_t)(n0 + r) * 256 + c64 + ch * 8);
        }
    };

    load_step(0, sb);
    CP_COMMIT();

    for (int ks = 0; ks < 16; ks++) {
        uint32_t bufb = sb + (ks & 1) * FBUF;
        if (ks + 1 < 16) load_step(ks + 1, sb + ((ks + 1) & 1) * FBUF);
        CP_COMMIT();
        CP_WAIT1();
        __syncthreads();

#pragma unroll
        for (int kc = 0; kc < 4; kc++) {
            uint32_t af[2][4];
#pragma unroll
            for (int t = 0; t < 2; t++)
                ldsm4(af[t], bufb + woff + t * 16 * FROW + kc * 32);
#pragma unroll
            for (int np = 0; np < 8; np++) {
                uint32_t xb4[4];
                ldsm4(xb4, bufb + xoff + np * 16 * FROW + kc * 32);
#pragma unroll
                for (int t = 0; t < 2; t++) {
                    mma16816(acc[t][2 * np],     af[t], xb4[0], xb4[1]);
                    mma16816(acc[t][2 * np + 1], af[t], xb4[2], xb4[3]);
                }
            }
        }
        __syncthreads();
    }

#pragma unroll
    for (int t = 0; t < 2; t++) {
        int o0 = obase + wrow + t * 16 + g;
#pragma unroll
        for (int nt = 0; nt < 16; nt++) {
            int n = n0 + nt * 8 + 2 * m;
            float* p = out + ((size_t)b * C_ + o0) * N_ + n;
            float* q = p + 8 * N_;
            p[0] = acc[t][nt][0]; p[1] = acc[t][nt][1];
            q[0] = acc[t][nt][2]; q[1] = acc[t][nt][3];
        }
    }
}

// ---------------------------------------------------------------------------
extern "C" void kernel_launch(void* const* d_in, const int* in_sizes, int n_in,
                              void* d_out, int out_size) {
    const float* x_f = (const float*)d_in[0];
    const float* x_b = (const float*)d_in[1];
    const float* Wq  = (const float*)d_in[2];
    const float* bq  = (const float*)d_in[3];
    const float* Wk  = (const float*)d_in[4];
    const float* bk  = (const float*)d_in[5];
    const float* Wv  = (const float*)d_in[6];
    const float* bv  = (const float*)d_in[7];
    const float* Wf  = (const float*)d_in[8];
    const float* bf  = (const float*)d_in[9];
    const float* gm  = (const float*)d_in[10];
    float* out = (float*)d_out;

    cudaFuncSetAttribute(attn_kernel, cudaFuncAttributeMaxDynamicSharedMemorySize, SM_TOTAL);
    cudaFuncSetAttribute(proj_all, cudaFuncAttributeMaxDynamicSharedMemorySize, SMP_TOTAL);
    cudaFuncSetAttribute(final_gemm, cudaFuncAttributeMaxDynamicSharedMemorySize, SMF_TOTAL);

    prep_w<<<256, 128>>>(Wf, gm, Wq, Wk, Wv);
    proj_all<<<dim3(N_ / 128, 1, K_ * B_ + B_), 256, SMP_TOTAL>>>(x_b, x_f, bq, bk, bv);
    attn_kernel<<<dim3(N_ / TI, K_ * B_), 128, SM_TOTAL>>>();
    prep_sum<<<(B_ * N_ * C_) / (256 * 8), 256>>>();
    final_gemm<<<dim3(N_ / 128, C_ / 128, B_), 128, SMF_TOTAL>>>(bf, out);
}